// round 1
// baseline (speedup 1.0000x reference)
#include <cuda_runtime.h>
#include <math.h>

// ---------------------------------------------------------------------------
// RegionOutputLayer: conv3x3(512->512)+BN+SiLU, conv1x1(512->425), YOLO decode
// B=16, H=W=40, NSP = 25600 spatial positions.
//
// conv1: implicit GEMM as 9 shifted 1x1 GEMMs (M=512, N=25600, K=512 per tap)
// conv2: GEMM (M=425 padded to 512, N=25600, K=512)
// Both use tf32 mma.sync m16n8k8, fp32 accumulate, RNA tf32 rounding.
// ---------------------------------------------------------------------------

namespace {
constexpr int CIN  = 512;
constexpr int CMID = 512;
constexpr int COUT = 425;
constexpr int NSP  = 25600;          // 16*40*40
constexpr int BM = 128, BN = 160, BK = 32;
constexpr int ASTR = 136;            // padded smem strides (bank-conflict free)
constexpr int BSTR = 168;
constexpr int ABUF = BK * ASTR;      // words per A buffer
constexpr int BBUF = BK * BSTR;      // words per B buffer
constexpr int SMEM_BYTES = (2 * ABUF + 2 * BBUF) * 4;   // 77824 B
}

// scratch (static device allocations are the allowed scratch mechanism)
__device__ float g_w1t[9 * CIN * CMID];          // [tap][cin][cmid]
__device__ float g_w2t[CIN * 512];               // [cin][cout padded to 512]
__device__ float g_s1[CMID];                     // BN scale
__device__ float g_b1[CMID];                     // BN shift
__device__ float g_h[(size_t)CMID * NSP];        // [cmid][n]
__device__ float g_det[(size_t)COUT * NSP];      // [cout][n]

static __device__ __forceinline__ unsigned f2tf32(float f) {
    unsigned u;
    asm("cvt.rna.tf32.f32 %0, %1;" : "=r"(u) : "f"(f));
    return u;
}

static __device__ __forceinline__ void mma8(float* c, const unsigned* a,
                                            unsigned b0, unsigned b1) {
    asm volatile(
        "mma.sync.aligned.m16n8k8.row.col.f32.tf32.tf32.f32 "
        "{%0,%1,%2,%3},{%4,%5,%6,%7},{%8,%9},{%0,%1,%2,%3};"
        : "+f"(c[0]), "+f"(c[1]), "+f"(c[2]), "+f"(c[3])
        : "r"(a[0]), "r"(a[1]), "r"(a[2]), "r"(a[3]), "r"(b0), "r"(b1));
}

static __device__ __forceinline__ float siluf(float x) {
    return x / (1.f + expf(-x));
}
static __device__ __forceinline__ float sigmoidf_(float x) {
    return 1.f / (1.f + expf(-x));
}

// ---------------------------------------------------------------------------
// prep: transpose weights, fold BN into scale/shift
// ---------------------------------------------------------------------------
__global__ void prep_kernel(const float* __restrict__ w1, const float* __restrict__ w2,
                            const float* __restrict__ gamma, const float* __restrict__ beta,
                            const float* __restrict__ mean, const float* __restrict__ var) {
    int i = blockIdx.x * 256 + threadIdx.x;
    if (i < 9 * CIN * CMID) {
        int cmid = i & 511;
        int cin  = (i >> 9) & 511;
        int tap  = i >> 18;
        g_w1t[i] = w1[(cmid * CIN + cin) * 9 + tap];
    }
    if (i < CIN * 512) {
        int cout = i & 511;
        int cin  = i >> 9;
        g_w2t[i] = (cout < COUT) ? w2[cout * CIN + cin] : 0.f;
    }
    if (i < CMID) {
        float s = gamma[i] * rsqrtf(var[i] + 1e-5f);
        g_s1[i] = s;
        g_b1[i] = beta[i] - mean[i] * s;
    }
}

// ---------------------------------------------------------------------------
// GEMM kernel (conv1 implicit 3x3 or conv2 1x1), tf32 mma.sync
// grid (160, 4), block 256 (8 warps: 4 m-warps x 2 n-warps)
// ---------------------------------------------------------------------------
template <bool CONV1>
__global__ void __launch_bounds__(256, 1)
conv_gemm(const float* __restrict__ xin, const float* __restrict__ bias2) {
    extern __shared__ unsigned smem[];
    unsigned* As = smem;
    unsigned* Bs = smem + 2 * ABUF;

    const int tid  = threadIdx.x;
    const int lane = tid & 31;
    const int warp = tid >> 5;
    const int wm   = (warp & 3) << 5;   // 32 rows per m-warp
    const int wn   = (warp >> 2) * 80;  // 80 cols per n-warp
    const int cmid0 = blockIdx.y * BM;
    const int n0    = blockIdx.x * BN;
    const int bimg  = blockIdx.x / 10;          // 10 n-tiles per image
    const int y0    = (blockIdx.x % 10) * 4;    // 4 rows per n-tile
    constexpr int S = CONV1 ? 144 : 16;         // 9 taps * 16 k-blocks | 16 k-blocks

    float acc[2][10][4];
#pragma unroll
    for (int i = 0; i < 2; i++)
#pragma unroll
        for (int j = 0; j < 10; j++)
#pragma unroll
            for (int k = 0; k < 4; k++) acc[i][j][k] = 0.f;

    float4 aR[4];
    float  bR[20];

    const float* bimgbase = CONV1 ? (xin + (size_t)bimg * CIN * 1600) : g_h;

    auto LOAD_A = [&](int s) {
        const float* ap;
        if (CONV1)
            ap = g_w1t + ((size_t)(s >> 4) * CIN + (size_t)(s & 15) * BK) * 512 + cmid0;
        else
            ap = g_w2t + (size_t)s * BK * 512 + cmid0;
#pragma unroll
        for (int j = 0; j < 4; j++) {
            int krel = (tid >> 5) + j * 8;
            int m    = (tid & 31) * 4;
            aR[j] = *reinterpret_cast<const float4*>(ap + krel * 512 + m);
        }
    };
    auto STORE_A = [&](int buf) {
        unsigned* ab = As + buf * ABUF;
#pragma unroll
        for (int j = 0; j < 4; j++) {
            int krel = (tid >> 5) + j * 8;
            int m    = (tid & 31) * 4;
            uint4 u = make_uint4(f2tf32(aR[j].x), f2tf32(aR[j].y),
                                 f2tf32(aR[j].z), f2tf32(aR[j].w));
            *reinterpret_cast<uint4*>(ab + krel * ASTR + m) = u;
        }
    };
    auto LOAD_B = [&](int s) {
        if (CONV1) {
            int tap = s >> 4;
            int dy1 = tap / 3 - 1;
            int dx1 = tap - (tap / 3) * 3 - 1;
            const float* bp = bimgbase + (size_t)((s & 15) * BK) * 1600;
            int krel = tid / 160;
            int rem  = tid - krel * 160;
            int yl   = rem / 40;
            int xl   = rem - yl * 40;
#pragma unroll
            for (int j = 0; j < 20; j++) {
                int yy = y0 + yl + dy1;
                int xx = xl + dx1;
                float v = 0.f;
                if ((unsigned)yy < 40u && (unsigned)xx < 40u)
                    v = __ldg(bp + krel * 1600 + yy * 40 + xx);
                bR[j] = v;
                krel += 1; yl += 2; xl += 16;           // advance by 256 positions
                if (xl >= 40) { xl -= 40; yl += 1; }
                if (yl >= 4)  { yl -= 4;  krel += 1; }
            }
        } else {
            const float* bp = g_h + (size_t)(s * BK) * NSP + n0;
#pragma unroll
            for (int j = 0; j < 5; j++) {
                int id   = tid + j * 256;
                int krel = id / 40;
                int n4   = id - krel * 40;
                *reinterpret_cast<float4*>(&bR[j * 4]) =
                    *reinterpret_cast<const float4*>(bp + (size_t)krel * NSP + n4 * 4);
            }
        }
    };
    auto STORE_B = [&](int buf) {
        unsigned* bb = Bs + buf * BBUF;
        if (CONV1) {
            int krel = tid / 160;
            int rem  = tid - krel * 160;
            int yl   = rem / 40;
            int xl   = rem - yl * 40;
#pragma unroll
            for (int j = 0; j < 20; j++) {
                bb[krel * BSTR + yl * 40 + xl] = f2tf32(bR[j]);
                krel += 1; yl += 2; xl += 16;
                if (xl >= 40) { xl -= 40; yl += 1; }
                if (yl >= 4)  { yl -= 4;  krel += 1; }
            }
        } else {
#pragma unroll
            for (int j = 0; j < 5; j++) {
                int id   = tid + j * 256;
                int krel = id / 40;
                int n4   = id - krel * 40;
                uint4 u = make_uint4(f2tf32(bR[j * 4 + 0]), f2tf32(bR[j * 4 + 1]),
                                     f2tf32(bR[j * 4 + 2]), f2tf32(bR[j * 4 + 3]));
                *reinterpret_cast<uint4*>(bb + krel * BSTR + n4 * 4) = u;
            }
        }
    };
    auto COMPUTE = [&](int buf) {
        const unsigned* ab = As + buf * ABUF;
        const unsigned* bb = Bs + buf * BBUF;
#pragma unroll
        for (int k8 = 0; k8 < 4; k8++) {
            int klo = k8 * 8 + (lane & 3);
            unsigned afr[2][4];
#pragma unroll
            for (int mf = 0; mf < 2; mf++) {
                int m = wm + mf * 16 + (lane >> 2);
                afr[mf][0] = ab[klo * ASTR + m];
                afr[mf][1] = ab[klo * ASTR + m + 8];
                afr[mf][2] = ab[(klo + 4) * ASTR + m];
                afr[mf][3] = ab[(klo + 4) * ASTR + m + 8];
            }
#pragma unroll
            for (int nf = 0; nf < 10; nf++) {
                int n = wn + nf * 8 + (lane >> 2);
                unsigned b0 = bb[klo * BSTR + n];
                unsigned b1 = bb[(klo + 4) * BSTR + n];
                mma8(acc[0][nf], afr[0], b0, b1);
                mma8(acc[1][nf], afr[1], b0, b1);
            }
        }
    };

    LOAD_A(0); LOAD_B(0);
    STORE_A(0); STORE_B(0);
    __syncthreads();
    for (int s = 0; s < S; ++s) {
        if (s + 1 < S) { LOAD_A(s + 1); LOAD_B(s + 1); }
        COMPUTE(s & 1);
        __syncthreads();
        if (s + 1 < S) {
            STORE_A((s + 1) & 1); STORE_B((s + 1) & 1);
            __syncthreads();
        }
    }

    // epilogue
#pragma unroll
    for (int mf = 0; mf < 2; mf++) {
        int r0 = cmid0 + wm + mf * 16 + (lane >> 2);
        int r1 = r0 + 8;
        if (CONV1) {
            float sA = g_s1[r0], bA = g_b1[r0];
            float sB = g_s1[r1], bB = g_b1[r1];
#pragma unroll
            for (int nf = 0; nf < 10; nf++) {
                int col = n0 + wn + nf * 8 + (lane & 3) * 2;
                float2 v01 = make_float2(siluf(acc[mf][nf][0] * sA + bA),
                                         siluf(acc[mf][nf][1] * sA + bA));
                float2 v23 = make_float2(siluf(acc[mf][nf][2] * sB + bB),
                                         siluf(acc[mf][nf][3] * sB + bB));
                *reinterpret_cast<float2*>(&g_h[(size_t)r0 * NSP + col]) = v01;
                *reinterpret_cast<float2*>(&g_h[(size_t)r1 * NSP + col]) = v23;
            }
        } else {
            float bA = (r0 < COUT) ? bias2[r0] : 0.f;
            float bB = (r1 < COUT) ? bias2[r1] : 0.f;
#pragma unroll
            for (int nf = 0; nf < 10; nf++) {
                int col = n0 + wn + nf * 8 + (lane & 3) * 2;
                if (r0 < COUT) {
                    float2 v = make_float2(acc[mf][nf][0] + bA, acc[mf][nf][1] + bA);
                    *reinterpret_cast<float2*>(&g_det[(size_t)r0 * NSP + col]) = v;
                }
                if (r1 < COUT) {
                    float2 v = make_float2(acc[mf][nf][2] + bB, acc[mf][nf][3] + bB);
                    *reinterpret_cast<float2*>(&g_det[(size_t)r1 * NSP + col]) = v;
                }
            }
        }
    }
}

// ---------------------------------------------------------------------------
// decode: boxes / objectness / softmax classes
// out layout: boxes [0,512000) | obj [512000,640000) | classes [640000,10880000)
// ---------------------------------------------------------------------------
__global__ void decode_kernel(const float* __restrict__ anchors, float* __restrict__ out) {
    int idx = blockIdx.x * blockDim.x + threadIdx.x;
    if (idx >= 5 * NSP) return;
    int n = idx % NSP;       // b*1600 + y*40 + x  (coalesced across threads)
    int a = idx / NSP;

    const float* dp = g_det + (size_t)(a * 85) * NSP + n;
    float d0 = dp[0];
    float d1 = dp[(size_t)1 * NSP];
    float d2 = dp[(size_t)2 * NSP];
    float d3 = dp[(size_t)3 * NSP];
    float d4 = dp[(size_t)4 * NSP];

    float cls[80];
    float mx = -1e30f;
#pragma unroll
    for (int c = 0; c < 80; c++) {
        float v = dp[(size_t)(5 + c) * NSP];
        cls[c] = v;
        mx = fmaxf(mx, v);
    }
    float sum = 0.f;
#pragma unroll
    for (int c = 0; c < 80; c++) {
        float e = expf(cls[c] - mx);
        cls[c] = e;
        sum += e;
    }
    float inv = 1.f / sum;

    int x = n % 40;
    int y = (n / 40) % 40;
    float bx = ((float)x + sigmoidf_(d0)) * (1.f / 40.f);
    float by = ((float)y + sigmoidf_(d1)) * (1.f / 40.f);
    float bw = anchors[2 * a]     * expf(d2);
    float bh = anchors[2 * a + 1] * expf(d3);

    *reinterpret_cast<float4*>(&out[(size_t)(n * 5 + a) * 4]) = make_float4(bx, by, bw, bh);
    out[512000 + n * 5 + a] = sigmoidf_(d4);

    float* co = out + 640000 + (size_t)(n * 5 + a) * 80;
#pragma unroll
    for (int c = 0; c < 80; c += 4) {
        *reinterpret_cast<float4*>(&co[c]) =
            make_float4(cls[c] * inv, cls[c + 1] * inv, cls[c + 2] * inv, cls[c + 3] * inv);
    }
}

// ---------------------------------------------------------------------------
extern "C" void kernel_launch(void* const* d_in, const int* in_sizes, int n_in,
                              void* d_out, int out_size) {
    const float* x       = (const float*)d_in[0];
    const float* w1      = (const float*)d_in[1];
    const float* gamma   = (const float*)d_in[2];
    const float* beta    = (const float*)d_in[3];
    const float* mean    = (const float*)d_in[4];
    const float* var     = (const float*)d_in[5];
    const float* w2      = (const float*)d_in[6];
    const float* b2      = (const float*)d_in[7];
    const float* anchors = (const float*)d_in[8];
    float* out = (float*)d_out;

    cudaFuncSetAttribute(conv_gemm<true>,  cudaFuncAttributeMaxDynamicSharedMemorySize, SMEM_BYTES);
    cudaFuncSetAttribute(conv_gemm<false>, cudaFuncAttributeMaxDynamicSharedMemorySize, SMEM_BYTES);

    prep_kernel<<<(9 * CIN * CMID + 255) / 256, 256>>>(w1, w2, gamma, beta, mean, var);
    conv_gemm<true><<<dim3(160, 4), 256, SMEM_BYTES>>>(x, nullptr);
    conv_gemm<false><<<dim3(160, 4), 256, SMEM_BYTES>>>(nullptr, b2);
    decode_kernel<<<(5 * NSP + 255) / 256, 256>>>(anchors, out);
}